// round 6
// baseline (speedup 1.0000x reference)
#include <cuda_runtime.h>
#include <cstdint>
#include <cstddef>

#define NTOK   98
#define CSTR   108
#define HEADS  4
#define DIM    128
#define BATCH  4096
#define NW     64
#define SCALE  0.17677669529663687f

__device__ float g_q[(size_t)BATCH * HEADS * NTOK * 32];
__device__ float g_k[(size_t)BATCH * HEADS * NTOK * 32];
__device__ float g_v[(size_t)BATCH * HEADS * NTOK * 32];
__device__ float g_o[(size_t)BATCH * NTOK * DIM];
__device__ float g_comb[(size_t)NW * HEADS * NTOK * CSTR];
__device__ float g_qkv_wr[384 * 128];
__device__ float g_proj_wr[128 * 128];

__device__ __forceinline__ int perm32(int d) { return ((d & 3) << 3) | (d >> 2); }

__device__ __forceinline__ float tf32r(float x) {
    unsigned u;
    asm("cvt.rna.tf32.f32 %0, %1;" : "=r"(u) : "f"(x));
    return __uint_as_float(u);
}
__device__ __forceinline__ float ex2f(float x) {
    float y;
    asm("ex2.approx.f32 %0, %1;" : "=f"(y) : "f"(x));
    return y;
}
__device__ __forceinline__ void mma8(float c[4], float a0, float a1, float a2, float a3,
                                     float b0, float b1) {
    asm volatile(
        "mma.sync.aligned.m16n8k8.row.col.f32.tf32.tf32.f32 "
        "{%0,%1,%2,%3},{%4,%5,%6,%7},{%8,%9},{%0,%1,%2,%3};\n"
        : "+f"(c[0]), "+f"(c[1]), "+f"(c[2]), "+f"(c[3])
        : "r"(__float_as_uint(a0)), "r"(__float_as_uint(a1)),
          "r"(__float_as_uint(a2)), "r"(__float_as_uint(a3)),
          "r"(__float_as_uint(b0)), "r"(__float_as_uint(b1)));
}
__device__ __forceinline__ void cp16(void* sptr, const void* gptr) {
    unsigned s = (unsigned)__cvta_generic_to_shared(sptr);
    asm volatile("cp.async.cg.shared.global [%0], [%1], 16;\n" :: "r"(s), "l"(gptr));
}
#define CP_COMMIT() asm volatile("cp.async.commit_group;\n" ::: "memory")
#define CP_WAIT0()  asm volatile("cp.async.wait_group 0;\n" ::: "memory")
#define CP_WAIT1()  asm volatile("cp.async.wait_group 1;\n" ::: "memory")

// ---------------- K-1: pre-round weights to tf32, permuted dim layout ----------------
__global__ void k_prep(const float* __restrict__ qkv_w, const float* __restrict__ proj_w) {
    int i = blockIdx.x * 256 + threadIdx.x;
    if (i < 384 * 128) {
        int n = i >> 7, d = i & 127;
        g_qkv_wr[(n << 7) + (d & ~31) + perm32(d & 31)] = tf32r(qkv_w[i]);
    }
    if (i < 128 * 128) {
        int n = i >> 7, d = i & 127;
        g_proj_wr[(n << 7) + (d & ~31) + perm32(d & 31)] = tf32r(proj_w[i]);
    }
}

// ---------------- K0: comb = mask + gathered bias, padded ----------------
__global__ void k_comb(const float* __restrict__ mask,
                       const float* __restrict__ rpb,
                       const int* __restrict__ relidx) {
    const int w = blockIdx.x >> 2, h = blockIdx.x & 3;
    float* dst = g_comb + (size_t)(w * HEADS + h) * NTOK * CSTR;
    const float* msk = mask + (size_t)w * NTOK * NTOK;
    for (int idx = threadIdx.x; idx < NTOK * CSTR; idx += blockDim.x) {
        int i = idx / CSTR, j = idx - i * CSTR;
        float v = -10000.0f;
        if (j < NTOK) v = msk[i * NTOK + j] + rpb[relidx[i * NTOK + j] * HEADS + h];
        dst[idx] = v;
    }
}

// ---------------- K1: QKV GEMM, resident A, cp.async B, vectorized B frags ----------------
#define QKV_SMEM_BYTES ((128 * 132 + 2 * 128 * 36) * 4)

__global__ void __launch_bounds__(256, 2) k_qkv(const float* __restrict__ x,
                                                const float* __restrict__ bias) {
    extern __shared__ float smq[];
    float (*As)[132] = reinterpret_cast<float(*)[132]>(smq);
    float* Bsbuf = smq + 128 * 132;                 // 2 x [128][36], permuted chunks
    const int m0 = blockIdx.x * 128;
    const int tid = threadIdx.x, lane = tid & 31, warp = tid >> 5;
    const int g = lane >> 2, tg = lane & 3;
    const int wm = warp >> 2, wn = warp & 3;
    const int fi = (tid & 7) * 4, r0 = tid >> 3;

    {   // load full 128x128 x tile once (rna-rounded, natural order)
        const int c = (tid & 31) * 4, rb = tid >> 5;
#pragma unroll
        for (int rr = 0; rr < 16; rr++) {
            int r = rb + rr * 8;
            float4 v4 = *reinterpret_cast<const float4*>(&x[(size_t)(m0 + r) * 128 + c]);
            *reinterpret_cast<float4*>(&As[r][c]) =
                make_float4(tf32r(v4.x), tf32r(v4.y), tf32r(v4.z), tf32r(v4.w));
        }
    }

    auto prefetchB = [&](int c, int buf) {
        const float* src = g_qkv_wr + (size_t)((c >> 2) * 128) * 128 + (c & 3) * 32;
        float* dst = Bsbuf + buf * (128 * 36);
#pragma unroll
        for (int rr = 0; rr < 4; rr++) {
            int r = r0 + rr * 32;
            cp16(&dst[r * 36 + fi], &src[(size_t)r * 128 + fi]);
        }
    };
    prefetchB(0, 0);
    CP_COMMIT();

    float c4[4][4][4];
    for (int c = 0; c < 12; c++) {
        const int kk = (c & 3) * 32;
        const float* Bs = Bsbuf + (c & 1) * (128 * 36);
        if ((c & 3) == 0) {
#pragma unroll
            for (int i = 0; i < 4; i++)
#pragma unroll
                for (int j = 0; j < 4; j++)
#pragma unroll
                    for (int q = 0; q < 4; q++) c4[i][j][q] = 0.f;
        }
        CP_WAIT0();
        __syncthreads();
        if (c + 1 < 12) { prefetchB(c + 1, (c + 1) & 1); CP_COMMIT(); }

        float bv[4][8];
#pragma unroll
        for (int ni = 0; ni < 4; ni++) {
            int cc = wn * 32 + ni * 8 + g;
            *reinterpret_cast<float4*>(&bv[ni][0]) =
                *reinterpret_cast<const float4*>(&Bs[cc * 36 + tg * 8]);
            *reinterpret_cast<float4*>(&bv[ni][4]) =
                *reinterpret_cast<const float4*>(&Bs[cc * 36 + tg * 8 + 4]);
        }
#pragma unroll
        for (int ks4 = 0; ks4 < 4; ks4++) {
            float a[4][4];
#pragma unroll
            for (int mi = 0; mi < 4; mi++) {
                int rr = wm * 64 + mi * 16 + g;
                a[mi][0] = As[rr][kk + ks4 * 8 + tg];     a[mi][1] = As[rr + 8][kk + ks4 * 8 + tg];
                a[mi][2] = As[rr][kk + ks4 * 8 + tg + 4]; a[mi][3] = As[rr + 8][kk + ks4 * 8 + tg + 4];
            }
#pragma unroll
            for (int mi = 0; mi < 4; mi++)
#pragma unroll
                for (int ni = 0; ni < 4; ni++)
                    mma8(c4[mi][ni], a[mi][0], a[mi][1], a[mi][2], a[mi][3],
                         bv[ni][2 * ks4], bv[ni][2 * ks4 + 1]);
        }
        __syncthreads();
        if ((c & 3) == 3) {
            int n0 = (c >> 2) * 128;
#pragma unroll
            for (int ni = 0; ni < 4; ni++) {
                int col = n0 + wn * 32 + ni * 8 + tg * 2;
                float b0 = bias[col], b1 = bias[col + 1];
                int sel = col >> 7, o = col & 127, h = o >> 5, d = o & 31;
                float* base = (sel == 0) ? g_q : ((sel == 1) ? g_k : g_v);
                int p0 = perm32(d), p1 = perm32(d + 1);
#pragma unroll
                for (int mi = 0; mi < 4; mi++) {
                    int m = m0 + wm * 64 + mi * 16 + g;
                    int b = m / NTOK, n = m - b * NTOK;
                    size_t idx = (((size_t)b * HEADS + h) * NTOK + n) * 32;
                    int m2 = m + 8, b2 = m2 / NTOK, n2 = m2 - b2 * NTOK;
                    size_t idx2 = (((size_t)b2 * HEADS + h) * NTOK + n2) * 32;
                    if (sel < 2) {   // q,k: permuted dim layout
                        base[idx + p0]  = c4[mi][ni][0] + b0;
                        base[idx + p1]  = c4[mi][ni][1] + b1;
                        base[idx2 + p0] = c4[mi][ni][2] + b0;
                        base[idx2 + p1] = c4[mi][ni][3] + b1;
                    } else {         // v: natural layout
                        *reinterpret_cast<float2*>(&base[idx + d]) =
                            make_float2(c4[mi][ni][0] + b0, c4[mi][ni][1] + b1);
                        *reinterpret_cast<float2*>(&base[idx2 + d]) =
                            make_float2(c4[mi][ni][2] + b0, c4[mi][ni][3] + b1);
                    }
                }
            }
        }
    }
}

// ---------------- K2: fused attention, occ-3, vectorized fragments ----------------
#define KSTR 36
#define VSTR 40
#define SM_KS (NTOK * CSTR)
#define SM_VS (SM_KS + 104 * KSTR)
#define ATTN_SMEM_BYTES ((SM_VS + 104 * VSTR) * 4)
#define ATHREADS 224

__global__ void __launch_bounds__(ATHREADS, 3) k_attn() {
    extern __shared__ float sm[];
    float* comb_s = sm;                 // [98][108]
    float* k_s = sm + SM_KS;            // [104][36], permuted dims
    float* v_s = sm + SM_VS;            // [104][40], natural dims

    const int t = blockIdx.x, h = blockIdx.y, w = blockIdx.z;
    const int tid = threadIdx.x, lane = tid & 31, warp = tid >> 5;
    const int g = lane >> 2, tg = lane & 3;
    const int r1 = warp * 16 + g, r2 = r1 + 8;
    const int cr1 = min(r1, NTOK - 1), cr2 = min(r2, NTOK - 1);
    const unsigned FULL = 0xffffffffu;
    const int o1 = (lane & ~3) + (tg >> 1), o2 = o1 + 2;
    const bool el = (tg & 1);
    const float L2E = 1.4426950408889634f;

    {
        const float* cg = g_comb + (size_t)(w * HEADS + h) * NTOK * CSTR;
        for (int i = tid; i < NTOK * CSTR; i += ATHREADS) comb_s[i] = cg[i];
    }
    for (int i = tid; i < 6 * KSTR; i += ATHREADS) k_s[98 * KSTR + i] = 0.f;
    for (int i = tid; i < 6 * VSTR; i += ATHREADS) v_s[98 * VSTR + i] = 0.f;

    for (int jj = 0; jj < 8; jj++) {
        const int b = (t * 8 + jj) * NW + w;
        const size_t off = ((size_t)b * HEADS + h) * NTOK * 32;
        const float* gq = g_q + off;
        const float* gk = g_k + off;
        const float* gv = g_v + off;

        __syncthreads();            // prior iteration's reads done
        for (int i = tid; i < 784; i += ATHREADS) {     // K (permuted rows, straight copy)
            int r = i >> 3, f = (i & 7) * 4;
            cp16(&k_s[r * KSTR + f], &gk[r * 32 + f]);
        }
        CP_COMMIT();
        for (int i = tid; i < 784; i += ATHREADS) {     // V
            int r = i >> 3, f = (i & 7) * 4;
            cp16(&v_s[r * VSTR + f], &gv[r * 32 + f]);
        }
        CP_COMMIT();

        // q fragments: 4 x LDG.128 (permuted layout) — overlaps the K wait
        float qa[4][4];
        {
            float qv1[8] = {0,0,0,0,0,0,0,0}, qv2[8] = {0,0,0,0,0,0,0,0};
            if (r1 < NTOK) {
                *reinterpret_cast<float4*>(&qv1[0]) =
                    *reinterpret_cast<const float4*>(&gq[r1 * 32 + tg * 8]);
                *reinterpret_cast<float4*>(&qv1[4]) =
                    *reinterpret_cast<const float4*>(&gq[r1 * 32 + tg * 8 + 4]);
            }
            if (r2 < NTOK) {
                *reinterpret_cast<float4*>(&qv2[0]) =
                    *reinterpret_cast<const float4*>(&gq[r2 * 32 + tg * 8]);
                *reinterpret_cast<float4*>(&qv2[4]) =
                    *reinterpret_cast<const float4*>(&gq[r2 * 32 + tg * 8 + 4]);
            }
#pragma unroll
            for (int ks4 = 0; ks4 < 4; ks4++) {
                qa[ks4][0] = tf32r(qv1[2 * ks4] * SCALE);
                qa[ks4][1] = tf32r(qv2[2 * ks4] * SCALE);
                qa[ks4][2] = tf32r(qv1[2 * ks4 + 1] * SCALE);
                qa[ks4][3] = tf32r(qv2[2 * ks4 + 1] * SCALE);
            }
        }
        CP_WAIT1();                 // K landed; V still in flight
        __syncthreads();

        // S = q @ k^T : vectorized K fragments (2 x LDS.128 per row-group)
        float s[13][4];
        const float* kbase = k_s + g * KSTR + tg * 8;
#pragma unroll
        for (int ni = 0; ni < 13; ni++) {
            float kv[8];
            *reinterpret_cast<float4*>(&kv[0]) =
                *reinterpret_cast<const float4*>(&kbase[ni * 8 * KSTR]);
            *reinterpret_cast<float4*>(&kv[4]) =
                *reinterpret_cast<const float4*>(&kbase[ni * 8 * KSTR + 4]);
            s[ni][0] = s[ni][1] = s[ni][2] = s[ni][3] = 0.f;
#pragma unroll
            for (int ks4 = 0; ks4 < 4; ks4++)
                mma8(s[ni], qa[ks4][0], qa[ks4][1], qa[ks4][2], qa[ks4][3],
                     kv[2 * ks4], kv[2 * ks4 + 1]);
        }
        // bias (float2) + quad softmax
        float m1 = -1e30f, m2 = -1e30f;
#pragma unroll
        for (int ni = 0; ni < 13; ni++) {
            int c0 = ni * 8 + tg * 2;
            float2 ca = *reinterpret_cast<const float2*>(&comb_s[cr1 * CSTR + c0]);
            float2 cb = *reinterpret_cast<const float2*>(&comb_s[cr2 * CSTR + c0]);
            s[ni][0] += ca.x; s[ni][1] += ca.y;
            s[ni][2] += cb.x; s[ni][3] += cb.y;
            m1 = fmaxf(m1, fmaxf(s[ni][0], s[ni][1]));
            m2 = fmaxf(m2, fmaxf(s[ni][2], s[ni][3]));
        }
        m1 = fmaxf(m1, __shfl_xor_sync(FULL, m1, 1));
        m1 = fmaxf(m1, __shfl_xor_sync(FULL, m1, 2));
        m2 = fmaxf(m2, __shfl_xor_sync(FULL, m2, 1));
        m2 = fmaxf(m2, __shfl_xor_sync(FULL, m2, 2));
        float sum1 = 0.f, sum2 = 0.f;
#pragma unroll
        for (int ni = 0; ni < 13; ni++) {
            s[ni][0] = tf32r(ex2f((s[ni][0] - m1) * L2E));
            s[ni][1] = tf32r(ex2f((s[ni][1] - m1) * L2E));
            s[ni][2] = tf32r(ex2f((s[ni][2] - m2) * L2E));
            s[ni][3] = tf32r(ex2f((s[ni][3] - m2) * L2E));
            sum1 += s[ni][0] + s[ni][1];
            sum2 += s[ni][2] + s[ni][3];
        }
        sum1 += __shfl_xor_sync(FULL, sum1, 1);
        sum1 += __shfl_xor_sync(FULL, sum1, 2);
        sum2 += __shfl_xor_sync(FULL, sum2, 1);
        sum2 += __shfl_xor_sync(FULL, sum2, 2);
        float inv1 = 1.0f / sum1, inv2 = 1.0f / sum2;

        CP_WAIT0();                 // V landed (hidden behind S + softmax)
        __syncthreads();

        // O = P @ V, P transposed C->A via intra-quad shfl
        float o[4][4];
#pragma unroll
        for (int ni = 0; ni < 4; ni++) o[ni][0] = o[ni][1] = o[ni][2] = o[ni][3] = 0.f;
#pragma unroll
        for (int kt = 0; kt < 13; kt++) {
            float v00 = __shfl_sync(FULL, s[kt][0], o1);
            float v01 = __shfl_sync(FULL, s[kt][1], o1);
            float v02 = __shfl_sync(FULL, s[kt][2], o1);
            float v03 = __shfl_sync(FULL, s[kt][3], o1);
            float a0 = el ? v01 : v00;
            float a1 = el ? v03 : v02;
            float w00 = __shfl_sync(FULL, s[kt][0], o2);
            float w01 = __shfl_sync(FULL, s[kt][1], o2);
            float w02 = __shfl_sync(FULL, s[kt][2], o2);
            float w03 = __shfl_sync(FULL, s[kt][3], o2);
            float a2 = el ? w01 : w00;
            float a3 = el ? w03 : w02;
#pragma unroll
            for (int ni = 0; ni < 4; ni++) {
                float b0 = v_s[(kt * 8 + tg) * VSTR + ni * 8 + g];
                float b1 = v_s[(kt * 8 + tg + 4) * VSTR + ni * 8 + g];
                mma8(o[ni], a0, a1, a2, a3, b0, b1);
            }
        }
        // store normalized O: permuted dims so k_proj A-frags vectorize
        float* gob = g_o + (size_t)b * NTOK * DIM + h * 32;
#pragma unroll
        for (int ni = 0; ni < 4; ni++) {
            int d0 = ni * 8 + tg * 2;
            int p0 = perm32(d0), p1 = perm32(d0 + 1);
            if (r1 < NTOK) {
                gob[r1 * DIM + p0] = tf32r(o[ni][0] * inv1);
                gob[r1 * DIM + p1] = tf32r(o[ni][1] * inv1);
            }
            if (r2 < NTOK) {
                gob[r2 * DIM + p0] = tf32r(o[ni][2] * inv2);
                gob[r2 * DIM + p1] = tf32r(o[ni][3] * inv2);
            }
        }
    }
}

// ---------------- K3: output projection, vectorized A+B fragments ----------------
#define PROJ_SMEM_BYTES (4 * 128 * 36 * 4)

__global__ void __launch_bounds__(256, 2) k_proj(const float* __restrict__ bias,
                                                 float* __restrict__ out) {
    extern __shared__ float smp[];
    float* Asb = smp;                   // 2 x [128][36], permuted chunks
    float* Bsb = smp + 2 * 128 * 36;    // 2 x [128][36], permuted chunks
    const int m0 = blockIdx.x * 128;
    const int tid = threadIdx.x, lane = tid & 31, warp = tid >> 5;
    const int g = lane >> 2, tg = lane & 3;
    const int wm = warp >> 2, wn = warp & 3;
    const int fi = (tid & 7) * 4, r0 = tid >> 3;

    auto prefetch = [&](int c, int buf) {
        const int kk = c * 32;
        float* ad = Asb + buf * (128 * 36);
        float* bd = Bsb + buf * (128 * 36);
#pragma unroll
        for (int rr = 0; rr < 4; rr++) {
            int r = r0 + rr * 32;
            cp16(&ad[r * 36 + fi], &g_o[(size_t)(m0 + r) * 128 + kk + fi]);
            cp16(&bd[r * 36 + fi], &g_proj_wr[(size_t)r * 128 + kk + fi]);
        }
    };
    prefetch(0, 0);
    CP_COMMIT();

    float c4[4][4][4];
#pragma unroll
    for (int i = 0; i < 4; i++)
#pragma unroll
        for (int j = 0; j < 4; j++)
#pragma unroll
            for (int q = 0; q < 4; q++) c4[i][j][q] = 0.f;

    for (int c = 0; c < 4; c++) {
        const float* As = Asb + (c & 1) * (128 * 36);
        const float* Bs = Bsb + (c & 1) * (128 * 36);
        CP_WAIT0();
        __syncthreads();
        if (c + 1 < 4) { prefetch(c + 1, (c + 1) & 1); CP_COMMIT(); }

        float bv[4][8];
#pragma unroll
        for (int ni = 0; ni < 4; ni++) {
            int cc = wn * 32 + ni * 8 + g;
            *reinterpret_cast<float4*>(&bv[ni][0]) =
                *reinterpret_cast<const float4*>(&Bs[cc * 36 + tg * 8]);
            *reinterpret_cast<float4*>(&bv[ni][4]) =
                *reinterpret_cast<const float4*>(&Bs[cc * 36 + tg * 8 + 4]);
        }
#pragma unroll
        for (int mi = 0; mi < 4; mi++) {
            int rr = wm * 64 + mi * 16 + g;
            float av1[8], av2[8];
            *reinterpret_cast<float4*>(&av1[0]) =
                *reinterpret_cast<const float4*>(&As[rr * 36 + tg * 8]);
            *reinterpret_cast<float4*>(&av1[4]) =
                *reinterpret_cast<const float4*>(&As[rr * 36 + tg * 8 + 4]);
            *reinterpret_cast<float4*>(&av2[0]) =
                *reinterpret_cast<const float4*>(&As[(rr + 8) * 36 + tg * 8]);
            *reinterpret_cast<float4*>(&av2[4]) =
                *reinterpret_cast<const float4*>(&As[(rr + 8) * 36 + tg * 8 + 4]);
#pragma unroll
            for (int ks4 = 0; ks4 < 4; ks4++)
#pragma unroll
                for (int ni = 0; ni < 4; ni++)
                    mma8(c4[mi][ni], av1[2 * ks4], av2[2 * ks4],
                         av1[2 * ks4 + 1], av2[2 * ks4 + 1],
                         bv[ni][2 * ks4], bv[ni][2 * ks4 + 1]);
        }
        __syncthreads();
    }
#pragma unroll
    for (int ni = 0; ni < 4; ni++) {
        int col = wn * 32 + ni * 8 + tg * 2;
        float b0 = bias[col], b1 = bias[col + 1];
#pragma unroll
        for (int mi = 0; mi < 4; mi++) {
            int m = m0 + wm * 64 + mi * 16 + g;
            *reinterpret_cast<float2*>(&out[(size_t)m * 128 + col]) =
                make_float2(c4[mi][ni][0] + b0, c4[mi][ni][1] + b1);
            *reinterpret_cast<float2*>(&out[(size_t)(m + 8) * 128 + col]) =
                make_float2(c4[mi][ni][2] + b0, c4[mi][ni][3] + b1);
        }
    }
}

extern "C" void kernel_launch(void* const* d_in, const int* in_sizes, int n_in,
                              void* d_out, int out_size) {
    const float* x      = (const float*)d_in[0];
    const float* mask   = (const float*)d_in[1];
    const float* rpb    = (const float*)d_in[2];
    const float* qkv_w  = (const float*)d_in[3];
    const float* qkv_b  = (const float*)d_in[4];
    const float* proj_w = (const float*)d_in[5];
    const float* proj_b = (const float*)d_in[6];
    const int*   relidx = (const int*)d_in[7];
    float* out = (float*)d_out;

    cudaFuncSetAttribute(k_qkv, cudaFuncAttributeMaxDynamicSharedMemorySize, QKV_SMEM_BYTES);
    cudaFuncSetAttribute(k_attn, cudaFuncAttributeMaxDynamicSharedMemorySize, ATTN_SMEM_BYTES);
    cudaFuncSetAttribute(k_proj, cudaFuncAttributeMaxDynamicSharedMemorySize, PROJ_SMEM_BYTES);

    k_prep<<<192, 256>>>(qkv_w, proj_w);
    k_comb<<<NW * HEADS, 256>>>(mask, rpb, relidx);
    k_qkv<<<BATCH * NTOK / 128, 256, QKV_SMEM_BYTES>>>(x, qkv_b);
    k_attn<<<dim3(8, HEADS, NW), ATHREADS, ATTN_SMEM_BYTES>>>();
    k_proj<<<BATCH * NTOK / 128, 256, PROJ_SMEM_BYTES>>>(proj_b, out);
}

// round 7
// speedup vs baseline: 1.2257x; 1.2257x over previous
#include <cuda_runtime.h>
#include <cuda_bf16.h>
#include <cstdint>
#include <cstddef>

#define NTOK   98
#define CSTR   108
#define HEADS  4
#define DIM    128
#define BATCH  4096
#define NW     64
#define SCALE  0.17677669529663687f

__device__ unsigned g_qb[(size_t)BATCH * HEADS * NTOK * 16];  // bf16x2 packed, q*SCALE
__device__ unsigned g_kb[(size_t)BATCH * HEADS * NTOK * 16];  // bf16x2 packed
__device__ float    g_v [(size_t)BATCH * HEADS * NTOK * 32];
__device__ float    g_o [(size_t)BATCH * NTOK * DIM];
__device__ float    g_comb[(size_t)NW * HEADS * NTOK * CSTR];
__device__ float    g_qkv_wr[384 * 128];
__device__ float    g_proj_wr[128 * 128];

__device__ __forceinline__ float tf32r(float x) {
    unsigned u;
    asm("cvt.rna.tf32.f32 %0, %1;" : "=r"(u) : "f"(x));
    return __uint_as_float(u);
}
__device__ __forceinline__ float ex2f(float x) {
    float y;
    asm("ex2.approx.f32 %0, %1;" : "=f"(y) : "f"(x));
    return y;
}
__device__ __forceinline__ unsigned bf2pack(float lo, float hi) {
    unsigned u;
    asm("cvt.rn.bf16x2.f32 %0, %1, %2;" : "=r"(u) : "f"(hi), "f"(lo));
    return u;
}
__device__ __forceinline__ void mma8(float c[4], float a0, float a1, float a2, float a3,
                                     float b0, float b1) {
    asm volatile(
        "mma.sync.aligned.m16n8k8.row.col.f32.tf32.tf32.f32 "
        "{%0,%1,%2,%3},{%4,%5,%6,%7},{%8,%9},{%0,%1,%2,%3};\n"
        : "+f"(c[0]), "+f"(c[1]), "+f"(c[2]), "+f"(c[3])
        : "r"(__float_as_uint(a0)), "r"(__float_as_uint(a1)),
          "r"(__float_as_uint(a2)), "r"(__float_as_uint(a3)),
          "r"(__float_as_uint(b0)), "r"(__float_as_uint(b1)));
}
__device__ __forceinline__ void mma16bf(float c[4], unsigned a0, unsigned a1,
                                        unsigned a2, unsigned a3,
                                        unsigned b0, unsigned b1) {
    asm volatile(
        "mma.sync.aligned.m16n8k16.row.col.f32.bf16.bf16.f32 "
        "{%0,%1,%2,%3},{%4,%5,%6,%7},{%8,%9},{%0,%1,%2,%3};\n"
        : "+f"(c[0]), "+f"(c[1]), "+f"(c[2]), "+f"(c[3])
        : "r"(a0), "r"(a1), "r"(a2), "r"(a3), "r"(b0), "r"(b1));
}
__device__ __forceinline__ void cp16(void* sptr, const void* gptr) {
    unsigned s = (unsigned)__cvta_generic_to_shared(sptr);
    asm volatile("cp.async.cg.shared.global [%0], [%1], 16;\n" :: "r"(s), "l"(gptr));
}
#define CP_COMMIT() asm volatile("cp.async.commit_group;\n" ::: "memory")
#define CP_WAIT0()  asm volatile("cp.async.wait_group 0;\n" ::: "memory")
#define CP_WAIT1()  asm volatile("cp.async.wait_group 1;\n" ::: "memory")

// ---------------- K-1: pre-round weights to tf32 ----------------
__global__ void k_prep(const float* __restrict__ qkv_w, const float* __restrict__ proj_w) {
    int i = blockIdx.x * 256 + threadIdx.x;
    if (i < 384 * 128) g_qkv_wr[i] = tf32r(qkv_w[i]);
    if (i < 128 * 128) g_proj_wr[i] = tf32r(proj_w[i]);
}

// ---------------- K0: comb = mask + gathered bias, padded ----------------
__global__ void k_comb(const float* __restrict__ mask,
                       const float* __restrict__ rpb,
                       const int* __restrict__ relidx) {
    const int w = blockIdx.x >> 2, h = blockIdx.x & 3;
    float* dst = g_comb + (size_t)(w * HEADS + h) * NTOK * CSTR;
    const float* msk = mask + (size_t)w * NTOK * NTOK;
    for (int idx = threadIdx.x; idx < NTOK * CSTR; idx += blockDim.x) {
        int i = idx / CSTR, j = idx - i * CSTR;
        float v = -10000.0f;
        if (j < NTOK) v = msk[i * NTOK + j] + rpb[relidx[i * NTOK + j] * HEADS + h];
        dst[idx] = v;
    }
}

// ---------------- K1: QKV GEMM, resident A, cp.async double-buffered B ----------------
#define QKV_SMEM_BYTES ((128 * 132 + 2 * 128 * 36) * 4)

__global__ void __launch_bounds__(256, 2) k_qkv(const float* __restrict__ x,
                                                const float* __restrict__ bias) {
    extern __shared__ float smq[];
    float (*As)[132] = reinterpret_cast<float(*)[132]>(smq);
    float* Bsbuf = smq + 128 * 132;                 // 2 x [128][36]
    const int m0 = blockIdx.x * 128;
    const int tid = threadIdx.x, lane = tid & 31, warp = tid >> 5;
    const int g = lane >> 2, tg = lane & 3;
    const int wm = warp >> 2, wn = warp & 3;
    const int fi = (tid & 7) * 4, r0 = tid >> 3;

    {   // load full 128x128 x tile once (rna-rounded)
        const int c = (tid & 31) * 4, rb = tid >> 5;
#pragma unroll
        for (int rr = 0; rr < 16; rr++) {
            int r = rb + rr * 8;
            float4 v4 = *reinterpret_cast<const float4*>(&x[(size_t)(m0 + r) * 128 + c]);
            *reinterpret_cast<float4*>(&As[r][c]) =
                make_float4(tf32r(v4.x), tf32r(v4.y), tf32r(v4.z), tf32r(v4.w));
        }
    }

    auto prefetchB = [&](int c, int buf) {
        const float* src = g_qkv_wr + (size_t)((c >> 2) * 128) * 128 + (c & 3) * 32;
        float* dst = Bsbuf + buf * (128 * 36);
#pragma unroll
        for (int rr = 0; rr < 4; rr++) {
            int r = r0 + rr * 32;
            cp16(&dst[r * 36 + fi], &src[(size_t)r * 128 + fi]);
        }
    };
    prefetchB(0, 0);
    CP_COMMIT();

    float c4[4][4][4];
    for (int c = 0; c < 12; c++) {
        const int kk = (c & 3) * 32;
        const float* Bs = Bsbuf + (c & 1) * (128 * 36);
        if ((c & 3) == 0) {
#pragma unroll
            for (int i = 0; i < 4; i++)
#pragma unroll
                for (int j = 0; j < 4; j++)
#pragma unroll
                    for (int q = 0; q < 4; q++) c4[i][j][q] = 0.f;
        }
        CP_WAIT0();
        __syncthreads();
        if (c + 1 < 12) { prefetchB(c + 1, (c + 1) & 1); CP_COMMIT(); }
#pragma unroll
        for (int ks = 0; ks < 32; ks += 8) {
            float a[4][4], bb[4][2];
#pragma unroll
            for (int mi = 0; mi < 4; mi++) {
                int rr = wm * 64 + mi * 16 + g;
                a[mi][0] = As[rr][kk + ks + tg];     a[mi][1] = As[rr + 8][kk + ks + tg];
                a[mi][2] = As[rr][kk + ks + tg + 4]; a[mi][3] = As[rr + 8][kk + ks + tg + 4];
            }
#pragma unroll
            for (int ni = 0; ni < 4; ni++) {
                int cc = wn * 32 + ni * 8 + g;
                bb[ni][0] = Bs[cc * 36 + ks + tg]; bb[ni][1] = Bs[cc * 36 + ks + tg + 4];
            }
#pragma unroll
            for (int mi = 0; mi < 4; mi++)
#pragma unroll
                for (int ni = 0; ni < 4; ni++)
                    mma8(c4[mi][ni], a[mi][0], a[mi][1], a[mi][2], a[mi][3],
                         bb[ni][0], bb[ni][1]);
        }
        __syncthreads();
        if ((c & 3) == 3) {   // epilogue for this n-tile
            int n0 = (c >> 2) * 128;
#pragma unroll
            for (int ni = 0; ni < 4; ni++) {
                int col = n0 + wn * 32 + ni * 8 + tg * 2;
                float b0 = bias[col], b1 = bias[col + 1];
                int sel = col >> 7, o = col & 127, h = o >> 5, d = o & 31;
#pragma unroll
                for (int mi = 0; mi < 4; mi++) {
                    int m = m0 + wm * 64 + mi * 16 + g;
                    int b = m / NTOK, n = m - b * NTOK;
                    int m2 = m + 8, b2 = m2 / NTOK, n2 = m2 - b2 * NTOK;
                    size_t i1 = ((size_t)b * HEADS + h) * NTOK + n;
                    size_t i2 = ((size_t)b2 * HEADS + h) * NTOK + n2;
                    if (sel == 2) {
                        *reinterpret_cast<float2*>(&g_v[i1 * 32 + d]) =
                            make_float2(c4[mi][ni][0] + b0, c4[mi][ni][1] + b1);
                        *reinterpret_cast<float2*>(&g_v[i2 * 32 + d]) =
                            make_float2(c4[mi][ni][2] + b0, c4[mi][ni][3] + b1);
                    } else {
                        float sc = (sel == 0) ? SCALE : 1.0f;
                        unsigned* base = (sel == 0) ? g_qb : g_kb;
                        base[i1 * 16 + (d >> 1)] =
                            bf2pack((c4[mi][ni][0] + b0) * sc, (c4[mi][ni][1] + b1) * sc);
                        base[i2 * 16 + (d >> 1)] =
                            bf2pack((c4[mi][ni][2] + b0) * sc, (c4[mi][ni][3] + b1) * sc);
                    }
                }
            }
        }
    }
}

// ---------------- K2: fused attention, bf16 QK^T + tf32 PV ----------------
#define KSU  20                        // k_s row stride in u32 (16 data + 4 pad)
#define VSTR 40
#define SM_KU (NTOK * CSTR)
#define SM_VS (SM_KU + 104 * KSU)
#define ATTN_SMEM_BYTES ((SM_VS + 104 * VSTR) * 4)
#define ATHREADS 224

__global__ void __launch_bounds__(ATHREADS, 3) k_attn() {
    extern __shared__ float sm[];
    float*    comb_s = sm;                                   // [98][108]
    unsigned* k_su = reinterpret_cast<unsigned*>(sm + SM_KU); // [104][20] bf16x2
    float*    v_s  = sm + SM_VS;                             // [104][40] fp32

    const int t = blockIdx.x, h = blockIdx.y, w = blockIdx.z;
    const int tid = threadIdx.x, lane = tid & 31, warp = tid >> 5;
    const int g = lane >> 2, tg = lane & 3;
    const int r1 = warp * 16 + g, r2 = r1 + 8;
    const int cr1 = min(r1, NTOK - 1), cr2 = min(r2, NTOK - 1);
    const unsigned FULL = 0xffffffffu;
    const int o1 = (lane & ~3) + (tg >> 1), o2 = o1 + 2;
    const bool el = (tg & 1);
    const float L2E = 1.4426950408889634f;

    {
        const float* cg = g_comb + (size_t)(w * HEADS + h) * NTOK * CSTR;
        for (int i = tid; i < NTOK * CSTR; i += ATHREADS) comb_s[i] = cg[i];
    }
    for (int i = tid; i < 6 * KSU; i += ATHREADS) k_su[98 * KSU + i] = 0u;
    for (int i = tid; i < 6 * VSTR; i += ATHREADS) v_s[98 * VSTR + i] = 0.f;

    for (int jj = 0; jj < 8; jj++) {
        const int b = (t * 8 + jj) * NW + w;
        const size_t bh = (size_t)b * HEADS + h;
        const unsigned* gqb = g_qb + bh * NTOK * 16;
        const unsigned* gkb = g_kb + bh * NTOK * 16;
        const float*    gv  = g_v  + bh * NTOK * 32;

        __syncthreads();            // prior iteration's reads done
        for (int i = tid; i < 392; i += ATHREADS) {     // K bf16: 98 rows x 4 cp16
            int r = i >> 2, c4i = (i & 3) * 4;
            cp16(&k_su[r * KSU + c4i], &gkb[r * 16 + c4i]);
        }
        CP_COMMIT();
        for (int i = tid; i < 784; i += ATHREADS) {     // V fp32: 98 rows x 8 cp16
            int r = i >> 3, f = (i & 7) * 4;
            cp16(&v_s[r * VSTR + f], &gv[r * 32 + f]);
        }
        CP_COMMIT();

        // q fragments (packed bf16x2, pre-scaled) — overlaps the K wait
        unsigned qu[2][4] = {{0u,0u,0u,0u},{0u,0u,0u,0u}};
        if (r1 < NTOK) {
            qu[0][0] = gqb[r1 * 16 + tg];     qu[0][2] = gqb[r1 * 16 + tg + 4];
            qu[1][0] = gqb[r1 * 16 + 8 + tg]; qu[1][2] = gqb[r1 * 16 + 8 + tg + 4];
        }
        if (r2 < NTOK) {
            qu[0][1] = gqb[r2 * 16 + tg];     qu[0][3] = gqb[r2 * 16 + tg + 4];
            qu[1][1] = gqb[r2 * 16 + 8 + tg]; qu[1][3] = gqb[r2 * 16 + 8 + tg + 4];
        }
        CP_WAIT1();                 // K landed; V still in flight
        __syncthreads();

        // S = q @ k^T (bf16 m16n8k16, 2 k-chunks)
        float s[13][4];
#pragma unroll
        for (int ni = 0; ni < 13; ni++)
            s[ni][0] = s[ni][1] = s[ni][2] = s[ni][3] = 0.f;
#pragma unroll
        for (int ch = 0; ch < 2; ch++) {
#pragma unroll
            for (int ni = 0; ni < 13; ni++) {
                unsigned b0 = k_su[(ni * 8 + g) * KSU + ch * 8 + tg];
                unsigned b1 = k_su[(ni * 8 + g) * KSU + ch * 8 + tg + 4];
                mma16bf(s[ni], qu[ch][0], qu[ch][1], qu[ch][2], qu[ch][3], b0, b1);
            }
        }
        // bias (float2) + quad softmax
        float m1 = -1e30f, m2 = -1e30f;
#pragma unroll
        for (int ni = 0; ni < 13; ni++) {
            int c0 = ni * 8 + tg * 2;
            float2 ca = *reinterpret_cast<const float2*>(&comb_s[cr1 * CSTR + c0]);
            float2 cb = *reinterpret_cast<const float2*>(&comb_s[cr2 * CSTR + c0]);
            s[ni][0] += ca.x; s[ni][1] += ca.y;
            s[ni][2] += cb.x; s[ni][3] += cb.y;
            m1 = fmaxf(m1, fmaxf(s[ni][0], s[ni][1]));
            m2 = fmaxf(m2, fmaxf(s[ni][2], s[ni][3]));
        }
        m1 = fmaxf(m1, __shfl_xor_sync(FULL, m1, 1));
        m1 = fmaxf(m1, __shfl_xor_sync(FULL, m1, 2));
        m2 = fmaxf(m2, __shfl_xor_sync(FULL, m2, 1));
        m2 = fmaxf(m2, __shfl_xor_sync(FULL, m2, 2));
        float sum1 = 0.f, sum2 = 0.f;
#pragma unroll
        for (int ni = 0; ni < 13; ni++) {
            s[ni][0] = tf32r(ex2f((s[ni][0] - m1) * L2E));
            s[ni][1] = tf32r(ex2f((s[ni][1] - m1) * L2E));
            s[ni][2] = tf32r(ex2f((s[ni][2] - m2) * L2E));
            s[ni][3] = tf32r(ex2f((s[ni][3] - m2) * L2E));
            sum1 += s[ni][0] + s[ni][1];
            sum2 += s[ni][2] + s[ni][3];
        }
        sum1 += __shfl_xor_sync(FULL, sum1, 1);
        sum1 += __shfl_xor_sync(FULL, sum1, 2);
        sum2 += __shfl_xor_sync(FULL, sum2, 1);
        sum2 += __shfl_xor_sync(FULL, sum2, 2);
        float inv1 = 1.0f / sum1, inv2 = 1.0f / sum2;

        CP_WAIT0();                 // V landed (hidden behind S + softmax)
        __syncthreads();

        // O = P @ V (tf32), P transposed C->A via intra-quad shfl
        float o[4][4];
#pragma unroll
        for (int ni = 0; ni < 4; ni++) o[ni][0] = o[ni][1] = o[ni][2] = o[ni][3] = 0.f;
#pragma unroll
        for (int kt = 0; kt < 13; kt++) {
            float v00 = __shfl_sync(FULL, s[kt][0], o1);
            float v01 = __shfl_sync(FULL, s[kt][1], o1);
            float v02 = __shfl_sync(FULL, s[kt][2], o1);
            float v03 = __shfl_sync(FULL, s[kt][3], o1);
            float a0 = el ? v01 : v00;
            float a1 = el ? v03 : v02;
            float w00 = __shfl_sync(FULL, s[kt][0], o2);
            float w01 = __shfl_sync(FULL, s[kt][1], o2);
            float w02 = __shfl_sync(FULL, s[kt][2], o2);
            float w03 = __shfl_sync(FULL, s[kt][3], o2);
            float a2 = el ? w01 : w00;
            float a3 = el ? w03 : w02;
#pragma unroll
            for (int ni = 0; ni < 4; ni++) {
                float b0 = v_s[(kt * 8 + tg) * VSTR + ni * 8 + g];
                float b1 = v_s[(kt * 8 + tg + 4) * VSTR + ni * 8 + g];
                mma8(o[ni], a0, a1, a2, a3, b0, b1);
            }
        }
        // store normalized O, tf32-rounded (coalesced float2)
        float* gob = g_o + (size_t)b * NTOK * DIM + h * 32;
#pragma unroll
        for (int ni = 0; ni < 4; ni++) {
            int d = ni * 8 + tg * 2;
            if (r1 < NTOK)
                *reinterpret_cast<float2*>(&gob[r1 * DIM + d]) =
                    make_float2(tf32r(o[ni][0] * inv1), tf32r(o[ni][1] * inv1));
            if (r2 < NTOK)
                *reinterpret_cast<float2*>(&gob[r2 * DIM + d]) =
                    make_float2(tf32r(o[ni][2] * inv2), tf32r(o[ni][3] * inv2));
        }
    }
}

// ---------------- K3: output projection, 3-stage cp.async pipeline ----------------
#define PROJ_SMEM_BYTES (6 * 128 * 36 * 4)

__global__ void __launch_bounds__(256, 2) k_proj(const float* __restrict__ bias,
                                                 float* __restrict__ out) {
    extern __shared__ float smp[];
    float* Asb = smp;                   // 3 x [128][36]
    float* Bsb = smp + 3 * 128 * 36;    // 3 x [128][36]
    const int m0 = blockIdx.x * 128;
    const int tid = threadIdx.x, lane = tid & 31, warp = tid >> 5;
    const int g = lane >> 2, tg = lane & 3;
    const int wm = warp >> 2, wn = warp & 3;
    const int fi = (tid & 7) * 4, r0 = tid >> 3;

    auto prefetch = [&](int c, int buf) {
        const int kk = c * 32;
        float* ad = Asb + buf * (128 * 36);
        float* bd = Bsb + buf * (128 * 36);
#pragma unroll
        for (int rr = 0; rr < 4; rr++) {
            int r = r0 + rr * 32;
            cp16(&ad[r * 36 + fi], &g_o[(size_t)(m0 + r) * 128 + kk + fi]);
            cp16(&bd[r * 36 + fi], &g_proj_wr[(size_t)r * 128 + kk + fi]);
        }
    };
    prefetch(0, 0); CP_COMMIT();
    prefetch(1, 1); CP_COMMIT();

    float c4[4][4][4];
#pragma unroll
    for (int i = 0; i < 4; i++)
#pragma unroll
        for (int j = 0; j < 4; j++)
#pragma unroll
            for (int q = 0; q < 4; q++) c4[i][j][q] = 0.f;

    for (int c = 0; c < 4; c++) {
        const int buf = c % 3;
        const float* As = Asb + buf * (128 * 36);
        const float* Bs = Bsb + buf * (128 * 36);
        CP_WAIT1();
        __syncthreads();
        if (c + 2 < 4) { prefetch(c + 2, (c + 2) % 3); CP_COMMIT(); }
#pragma unroll
        for (int ks = 0; ks < 32; ks += 8) {
            float a[4][4], bb[4][2];
#pragma unroll
            for (int mi = 0; mi < 4; mi++) {
                int rr = wm * 64 + mi * 16 + g;
                a[mi][0] = As[rr * 36 + ks + tg];     a[mi][1] = As[(rr + 8) * 36 + ks + tg];
                a[mi][2] = As[rr * 36 + ks + tg + 4]; a[mi][3] = As[(rr + 8) * 36 + ks + tg + 4];
            }
#pragma unroll
            for (int ni = 0; ni < 4; ni++) {
                int cc = wn * 32 + ni * 8 + g;
                bb[ni][0] = Bs[cc * 36 + ks + tg]; bb[ni][1] = Bs[cc * 36 + ks + tg + 4];
            }
#pragma unroll
            for (int mi = 0; mi < 4; mi++)
#pragma unroll
                for (int ni = 0; ni < 4; ni++)
                    mma8(c4[mi][ni], a[mi][0], a[mi][1], a[mi][2], a[mi][3],
                         bb[ni][0], bb[ni][1]);
        }
        __syncthreads();
    }
#pragma unroll
    for (int ni = 0; ni < 4; ni++) {
        int col = wn * 32 + ni * 8 + tg * 2;
        float b0 = bias[col], b1 = bias[col + 1];
#pragma unroll
        for (int mi = 0; mi < 4; mi++) {
            int m = m0 + wm * 64 + mi * 16 + g;
            *reinterpret_cast<float2*>(&out[(size_t)m * 128 + col]) =
                make_float2(c4[mi][ni][0] + b0, c4[mi][ni][1] + b1);
            *reinterpret_cast<float2*>(&out[(size_t)(m + 8) * 128 + col]) =
                make_float2(c4[mi][ni][2] + b0, c4[mi][ni][3] + b1);
        }
    }
}

extern "C" void kernel_launch(void* const* d_in, const int* in_sizes, int n_in,
                              void* d_out, int out_size) {
    const float* x      = (const float*)d_in[0];
    const float* mask   = (const float*)d_in[1];
    const float* rpb    = (const float*)d_in[2];
    const float* qkv_w  = (const float*)d_in[3];
    const float* qkv_b  = (const float*)d_in[4];
    const float* proj_w = (const float*)d_in[5];
    const float* proj_b = (const float*)d_in[6];
    const int*   relidx = (const int*)d_in[7];
    float* out = (float*)d_out;

    cudaFuncSetAttribute(k_qkv, cudaFuncAttributeMaxDynamicSharedMemorySize, QKV_SMEM_BYTES);
    cudaFuncSetAttribute(k_attn, cudaFuncAttributeMaxDynamicSharedMemorySize, ATTN_SMEM_BYTES);
    cudaFuncSetAttribute(k_proj, cudaFuncAttributeMaxDynamicSharedMemorySize, PROJ_SMEM_BYTES);

    k_prep<<<192, 256>>>(qkv_w, proj_w);
    k_comb<<<NW * HEADS, 256>>>(mask, rpb, relidx);
    k_qkv<<<BATCH * NTOK / 128, 256, QKV_SMEM_BYTES>>>(x, qkv_b);
    k_attn<<<dim3(8, HEADS, NW), ATHREADS, ATTN_SMEM_BYTES>>>();
    k_proj<<<BATCH * NTOK / 128, 256, PROJ_SMEM_BYTES>>>(proj_b, out);
}

// round 8
// speedup vs baseline: 1.3443x; 1.0967x over previous
#include <cuda_runtime.h>
#include <cuda_fp16.h>
#include <cstdint>
#include <cstddef>

#define NTOK   98
#define CSTR   108
#define HEADS  4
#define DIM    128
#define BATCH  4096
#define NW     64
#define SCALE  0.17677669529663687f

__device__ unsigned g_qb[(size_t)BATCH * HEADS * NTOK * 16];  // f16x2 packed, q*SCALE
__device__ unsigned g_kb[(size_t)BATCH * HEADS * NTOK * 16];  // f16x2 packed
__device__ __half   g_vh[(size_t)BATCH * HEADS * 32 * 112];   // V transposed [dim][tok], pads 0
__device__ float    g_o [(size_t)BATCH * NTOK * DIM];
__device__ float    g_comb[(size_t)NW * HEADS * NTOK * CSTR];
__device__ float    g_qkv_wr[384 * 128];
__device__ float    g_proj_wr[128 * 128];

__device__ __forceinline__ float tf32r(float x) {
    unsigned u;
    asm("cvt.rna.tf32.f32 %0, %1;" : "=r"(u) : "f"(x));
    return __uint_as_float(u);
}
__device__ __forceinline__ float ex2f(float x) {
    float y;
    asm("ex2.approx.f32 %0, %1;" : "=f"(y) : "f"(x));
    return y;
}
__device__ __forceinline__ unsigned h2pack(float lo, float hi) {
    unsigned u;
    asm("cvt.rn.f16x2.f32 %0, %1, %2;" : "=r"(u) : "f"(hi), "f"(lo));
    return u;
}
__device__ __forceinline__ void mma8(float c[4], float a0, float a1, float a2, float a3,
                                     float b0, float b1) {
    asm volatile(
        "mma.sync.aligned.m16n8k8.row.col.f32.tf32.tf32.f32 "
        "{%0,%1,%2,%3},{%4,%5,%6,%7},{%8,%9},{%0,%1,%2,%3};\n"
        : "+f"(c[0]), "+f"(c[1]), "+f"(c[2]), "+f"(c[3])
        : "r"(__float_as_uint(a0)), "r"(__float_as_uint(a1)),
          "r"(__float_as_uint(a2)), "r"(__float_as_uint(a3)),
          "r"(__float_as_uint(b0)), "r"(__float_as_uint(b1)));
}
__device__ __forceinline__ void mma16h(float c[4], unsigned a0, unsigned a1,
                                       unsigned a2, unsigned a3,
                                       unsigned b0, unsigned b1) {
    asm volatile(
        "mma.sync.aligned.m16n8k16.row.col.f32.f16.f16.f32 "
        "{%0,%1,%2,%3},{%4,%5,%6,%7},{%8,%9},{%0,%1,%2,%3};\n"
        : "+f"(c[0]), "+f"(c[1]), "+f"(c[2]), "+f"(c[3])
        : "r"(a0), "r"(a1), "r"(a2), "r"(a3), "r"(b0), "r"(b1));
}
__device__ __forceinline__ void cp16(void* sptr, const void* gptr) {
    unsigned s = (unsigned)__cvta_generic_to_shared(sptr);
    asm volatile("cp.async.cg.shared.global [%0], [%1], 16;\n" :: "r"(s), "l"(gptr));
}
#define CP_COMMIT() asm volatile("cp.async.commit_group;\n" ::: "memory")
#define CP_WAIT0()  asm volatile("cp.async.wait_group 0;\n" ::: "memory")
#define CP_WAIT1()  asm volatile("cp.async.wait_group 1;\n" ::: "memory")

// ---------------- K-1: pre-round weights to tf32 ----------------
__global__ void k_prep(const float* __restrict__ qkv_w, const float* __restrict__ proj_w) {
    int i = blockIdx.x * 256 + threadIdx.x;
    if (i < 384 * 128) g_qkv_wr[i] = tf32r(qkv_w[i]);
    if (i < 128 * 128) g_proj_wr[i] = tf32r(proj_w[i]);
}

// ---------------- K0: comb = mask + gathered bias, padded ----------------
__global__ void k_comb(const float* __restrict__ mask,
                       const float* __restrict__ rpb,
                       const int* __restrict__ relidx) {
    const int w = blockIdx.x >> 2, h = blockIdx.x & 3;
    float* dst = g_comb + (size_t)(w * HEADS + h) * NTOK * CSTR;
    const float* msk = mask + (size_t)w * NTOK * NTOK;
    for (int idx = threadIdx.x; idx < NTOK * CSTR; idx += blockDim.x) {
        int i = idx / CSTR, j = idx - i * CSTR;
        float v = -10000.0f;
        if (j < NTOK) v = msk[i * NTOK + j] + rpb[relidx[i * NTOK + j] * HEADS + h];
        dst[idx] = v;
    }
}

// ---------------- K1: QKV GEMM (tf32), fp16 epilogue ----------------
#define QKV_SMEM_BYTES ((128 * 132 + 2 * 128 * 36) * 4)

__global__ void __launch_bounds__(256, 2) k_qkv(const float* __restrict__ x,
                                                const float* __restrict__ bias) {
    extern __shared__ float smq[];
    float (*As)[132] = reinterpret_cast<float(*)[132]>(smq);
    float* Bsbuf = smq + 128 * 132;
    const int m0 = blockIdx.x * 128;
    const int tid = threadIdx.x, lane = tid & 31, warp = tid >> 5;
    const int g = lane >> 2, tg = lane & 3;
    const int wm = warp >> 2, wn = warp & 3;
    const int fi = (tid & 7) * 4, r0 = tid >> 3;

    {   // load full 128x128 x tile once (rna-rounded)
        const int c = (tid & 31) * 4, rb = tid >> 5;
#pragma unroll
        for (int rr = 0; rr < 16; rr++) {
            int r = rb + rr * 8;
            float4 v4 = *reinterpret_cast<const float4*>(&x[(size_t)(m0 + r) * 128 + c]);
            *reinterpret_cast<float4*>(&As[r][c]) =
                make_float4(tf32r(v4.x), tf32r(v4.y), tf32r(v4.z), tf32r(v4.w));
        }
    }

    auto prefetchB = [&](int c, int buf) {
        const float* src = g_qkv_wr + (size_t)((c >> 2) * 128) * 128 + (c & 3) * 32;
        float* dst = Bsbuf + buf * (128 * 36);
#pragma unroll
        for (int rr = 0; rr < 4; rr++) {
            int r = r0 + rr * 32;
            cp16(&dst[r * 36 + fi], &src[(size_t)r * 128 + fi]);
        }
    };
    prefetchB(0, 0);
    CP_COMMIT();

    float c4[4][4][4];
    for (int c = 0; c < 12; c++) {
        const int kk = (c & 3) * 32;
        const float* Bs = Bsbuf + (c & 1) * (128 * 36);
        if ((c & 3) == 0) {
#pragma unroll
            for (int i = 0; i < 4; i++)
#pragma unroll
                for (int j = 0; j < 4; j++)
#pragma unroll
                    for (int q = 0; q < 4; q++) c4[i][j][q] = 0.f;
        }
        CP_WAIT0();
        __syncthreads();
        if (c + 1 < 12) { prefetchB(c + 1, (c + 1) & 1); CP_COMMIT(); }
#pragma unroll
        for (int ks = 0; ks < 32; ks += 8) {
            float a[4][4], bb[4][2];
#pragma unroll
            for (int mi = 0; mi < 4; mi++) {
                int rr = wm * 64 + mi * 16 + g;
                a[mi][0] = As[rr][kk + ks + tg];     a[mi][1] = As[rr + 8][kk + ks + tg];
                a[mi][2] = As[rr][kk + ks + tg + 4]; a[mi][3] = As[rr + 8][kk + ks + tg + 4];
            }
#pragma unroll
            for (int ni = 0; ni < 4; ni++) {
                int cc = wn * 32 + ni * 8 + g;
                bb[ni][0] = Bs[cc * 36 + ks + tg]; bb[ni][1] = Bs[cc * 36 + ks + tg + 4];
            }
#pragma unroll
            for (int mi = 0; mi < 4; mi++)
#pragma unroll
                for (int ni = 0; ni < 4; ni++)
                    mma8(c4[mi][ni], a[mi][0], a[mi][1], a[mi][2], a[mi][3],
                         bb[ni][0], bb[ni][1]);
        }
        __syncthreads();
        if ((c & 3) == 3) {   // epilogue for this n-tile
            int n0 = (c >> 2) * 128;
#pragma unroll
            for (int ni = 0; ni < 4; ni++) {
                int col = n0 + wn * 32 + ni * 8 + tg * 2;
                float b0 = bias[col], b1 = bias[col + 1];
                int sel = col >> 7, o = col & 127, h = o >> 5, d = o & 31;
#pragma unroll
                for (int mi = 0; mi < 4; mi++) {
                    int m = m0 + wm * 64 + mi * 16 + g;
                    int b = m / NTOK, n = m - b * NTOK;
                    int m2 = m + 8, b2 = m2 / NTOK, n2 = m2 - b2 * NTOK;
                    size_t bh1 = (size_t)b * HEADS + h;
                    size_t bh2 = (size_t)b2 * HEADS + h;
                    if (sel == 2) {   // V: fp16 transposed [dim][112 tok]
                        g_vh[(bh1 * 32 + d)     * 112 + n]  = __float2half(c4[mi][ni][0] + b0);
                        g_vh[(bh1 * 32 + d + 1) * 112 + n]  = __float2half(c4[mi][ni][1] + b1);
                        g_vh[(bh2 * 32 + d)     * 112 + n2] = __float2half(c4[mi][ni][2] + b0);
                        g_vh[(bh2 * 32 + d + 1) * 112 + n2] = __float2half(c4[mi][ni][3] + b1);
                    } else {          // q,k: fp16x2 packed
                        float sc = (sel == 0) ? SCALE : 1.0f;
                        unsigned* base = (sel == 0) ? g_qb : g_kb;
                        base[(bh1 * NTOK + n)  * 16 + (d >> 1)] =
                            h2pack((c4[mi][ni][0] + b0) * sc, (c4[mi][ni][1] + b1) * sc);
                        base[(bh2 * NTOK + n2) * 16 + (d >> 1)] =
                            h2pack((c4[mi][ni][2] + b0) * sc, (c4[mi][ni][3] + b1) * sc);
                    }
                }
            }
        }
    }
}

// ---------------- K2: fused attention, fp16 QK^T + fp16 PV (FA2 P-reuse) ----------------
#define KSU  20                       // K row stride (u32): 16 data + 4 pad
#define VTU  60                       // V_t row stride (u32): 56 data + 4 pad
#define SM_KU (NTOK * CSTR)           // float offsets
#define SM_VU (SM_KU + 104 * KSU)
#define ATTN_SMEM_BYTES ((SM_VU + 32 * VTU) * 4)
#define ATHREADS 224

__global__ void __launch_bounds__(ATHREADS, 3) k_attn() {
    extern __shared__ float sm[];
    float*    comb_s = sm;                                     // [98][108] fp32
    unsigned* k_su = reinterpret_cast<unsigned*>(sm + SM_KU);  // [104][20] f16x2
    unsigned* v_su = reinterpret_cast<unsigned*>(sm + SM_VU);  // [32][60]  f16x2 (V_t)

    const int t = blockIdx.x, h = blockIdx.y, w = blockIdx.z;
    const int tid = threadIdx.x, lane = tid & 31, warp = tid >> 5;
    const int g = lane >> 2, tg = lane & 3;
    const int r1 = warp * 16 + g, r2 = r1 + 8;
    const int cr1 = min(r1, NTOK - 1), cr2 = min(r2, NTOK - 1);
    const unsigned FULL = 0xffffffffu;
    const float L2E = 1.4426950408889634f;

    {
        const float* cg = g_comb + (size_t)(w * HEADS + h) * NTOK * CSTR;
        for (int i = tid; i < NTOK * CSTR; i += ATHREADS) comb_s[i] = cg[i];
    }
    // zero K pad rows 98..103 (never written by cp.async)
    for (int i = tid; i < 6 * KSU; i += ATHREADS) k_su[98 * KSU + i] = 0u;

    for (int jj = 0; jj < 8; jj++) {
        const int b = (t * 8 + jj) * NW + w;
        const size_t bh = (size_t)b * HEADS + h;
        const unsigned* gqb = g_qb + bh * NTOK * 16;
        const unsigned* gkb = g_kb + bh * NTOK * 16;
        const __half*   gvh = g_vh + bh * 32 * 112;

        __syncthreads();            // prior iteration's smem reads done
        for (int i = tid; i < 392; i += ATHREADS) {     // K: 98 rows x 4 cp16
            int r = i >> 2, c = (i & 3) * 4;
            cp16(&k_su[r * KSU + c], &gkb[r * 16 + c]);
        }
        CP_COMMIT();
        for (int i = tid; i < 448; i += ATHREADS) {     // V_t: 32 rows x 14 cp16
            int r = i / 14, c = i - r * 14;
            cp16(&v_su[r * VTU + c * 4], &gvh[r * 112 + c * 8]);
        }
        CP_COMMIT();

        // q fragments (packed f16x2, pre-scaled) — overlaps the K wait
        unsigned qu[2][4] = {{0u,0u,0u,0u},{0u,0u,0u,0u}};
        if (r1 < NTOK) {
            qu[0][0] = gqb[r1 * 16 + tg];     qu[0][2] = gqb[r1 * 16 + tg + 4];
            qu[1][0] = gqb[r1 * 16 + 8 + tg]; qu[1][2] = gqb[r1 * 16 + 8 + tg + 4];
        }
        if (r2 < NTOK) {
            qu[0][1] = gqb[r2 * 16 + tg];     qu[0][3] = gqb[r2 * 16 + tg + 4];
            qu[1][1] = gqb[r2 * 16 + 8 + tg]; qu[1][3] = gqb[r2 * 16 + 8 + tg + 4];
        }
        CP_WAIT1();                 // K landed; V_t still in flight
        __syncthreads();

        // S = q @ k^T (f16 m16n8k16, 2 dim-chunks)
        float s[13][4];
#pragma unroll
        for (int ni = 0; ni < 13; ni++)
            s[ni][0] = s[ni][1] = s[ni][2] = s[ni][3] = 0.f;
#pragma unroll
        for (int ch = 0; ch < 2; ch++) {
#pragma unroll
            for (int ni = 0; ni < 13; ni++) {
                unsigned b0 = k_su[(ni * 8 + g) * KSU + ch * 8 + tg];
                unsigned b1 = k_su[(ni * 8 + g) * KSU + ch * 8 + tg + 4];
                mma16h(s[ni], qu[ch][0], qu[ch][1], qu[ch][2], qu[ch][3], b0, b1);
            }
        }
        // bias (float2) + quad softmax
        float m1 = -1e30f, m2 = -1e30f;
#pragma unroll
        for (int ni = 0; ni < 13; ni++) {
            int c0 = ni * 8 + tg * 2;
            float2 ca = *reinterpret_cast<const float2*>(&comb_s[cr1 * CSTR + c0]);
            float2 cb = *reinterpret_cast<const float2*>(&comb_s[cr2 * CSTR + c0]);
            s[ni][0] += ca.x; s[ni][1] += ca.y;
            s[ni][2] += cb.x; s[ni][3] += cb.y;
            m1 = fmaxf(m1, fmaxf(s[ni][0], s[ni][1]));
            m2 = fmaxf(m2, fmaxf(s[ni][2], s[ni][3]));
        }
        m1 = fmaxf(m1, __shfl_xor_sync(FULL, m1, 1));
        m1 = fmaxf(m1, __shfl_xor_sync(FULL, m1, 2));
        m2 = fmaxf(m2, __shfl_xor_sync(FULL, m2, 1));
        m2 = fmaxf(m2, __shfl_xor_sync(FULL, m2, 2));
        float sum1 = 0.f, sum2 = 0.f;
#pragma unroll
        for (int ni = 0; ni < 13; ni++) {
            s[ni][0] = ex2f((s[ni][0] - m1) * L2E);
            s[ni][1] = ex2f((s[ni][1] - m1) * L2E);
            s[ni][2] = ex2f((s[ni][2] - m2) * L2E);
            s[ni][3] = ex2f((s[ni][3] - m2) * L2E);
            sum1 += s[ni][0] + s[ni][1];
            sum2 += s[ni][2] + s[ni][3];
        }
        sum1 += __shfl_xor_sync(FULL, sum1, 1);
        sum1 += __shfl_xor_sync(FULL, sum1, 2);
        sum2 += __shfl_xor_sync(FULL, sum2, 1);
        sum2 += __shfl_xor_sync(FULL, sum2, 2);
        float inv1 = 1.0f / sum1, inv2 = 1.0f / sum2;

        CP_WAIT0();                 // V_t landed (hidden behind S + softmax)
        __syncthreads();

        // O = P @ V : P accumulators repacked directly as f16 A-fragments (no shfl)
        float o[4][4];
#pragma unroll
        for (int ni = 0; ni < 4; ni++) o[ni][0] = o[ni][1] = o[ni][2] = o[ni][3] = 0.f;
#pragma unroll
        for (int kt = 0; kt < 7; kt++) {
            unsigned a0 = h2pack(s[2 * kt][0], s[2 * kt][1]);
            unsigned a1 = h2pack(s[2 * kt][2], s[2 * kt][3]);
            unsigned a2 = 0u, a3 = 0u;
            if (kt < 6) {
                a2 = h2pack(s[2 * kt + 1][0], s[2 * kt + 1][1]);
                a3 = h2pack(s[2 * kt + 1][2], s[2 * kt + 1][3]);
            }
#pragma unroll
            for (int ni = 0; ni < 4; ni++) {
                unsigned b0 = v_su[(ni * 8 + g) * VTU + 8 * kt + tg];
                unsigned b1 = v_su[(ni * 8 + g) * VTU + 8 * kt + tg + 4];
                mma16h(o[ni], a0, a1, a2, a3, b0, b1);
            }
        }
        // store normalized O, tf32-rounded (coalesced float2)
        float* gob = g_o + (size_t)b * NTOK * DIM + h * 32;
#pragma unroll
        for (int ni = 0; ni < 4; ni++) {
            int d = ni * 8 + tg * 2;
            if (r1 < NTOK)
                *reinterpret_cast<float2*>(&gob[r1 * DIM + d]) =
                    make_float2(tf32r(o[ni][0] * inv1), tf32r(o[ni][1] * inv1));
            if (r2 < NTOK)
                *reinterpret_cast<float2*>(&gob[r2 * DIM + d]) =
                    make_float2(tf32r(o[ni][2] * inv2), tf32r(o[ni][3] * inv2));
        }
    }
}

// ---------------- K3: output projection, 3-stage cp.async pipeline ----------------
#define PROJ_SMEM_BYTES (6 * 128 * 36 * 4)

__global__ void __launch_bounds__(256, 2) k_proj(const float* __restrict__ bias,
                                                 float* __restrict__ out) {
    extern __shared__ float smp[];
    float* Asb = smp;                   // 3 x [128][36]
    float* Bsb = smp + 3 * 128 * 36;    // 3 x [128][36]
    const int m0 = blockIdx.x * 128;
    const int tid = threadIdx.x, lane = tid & 31, warp = tid >> 5;
    const int g = lane >> 2, tg = lane & 3;
    const int wm = warp >> 2, wn = warp & 3;
    const int fi = (tid & 7) * 4, r0 = tid >> 3;

    auto prefetch = [&](int c, int buf) {
        const int kk = c * 32;
        float* ad = Asb + buf * (128 * 36);
        float* bd = Bsb + buf * (128 * 36);
#pragma unroll
        for (int rr = 0; rr < 4; rr++) {
            int r = r0 + rr * 32;
            cp16(&ad[r * 36 + fi], &g_o[(size_t)(m0 + r) * 128 + kk + fi]);
            cp16(&bd[r * 36 + fi], &g_proj_wr[(size_t)r * 128 + kk + fi]);
        }
    };
    prefetch(0, 0); CP_COMMIT();
    prefetch(1, 1); CP_COMMIT();

    float c4[4][4][4];
#pragma unroll
    for (int i = 0; i < 4; i++)
#pragma unroll
        for (int j = 0; j < 4; j++)
#pragma unroll
            for (int q = 0; q < 4; q++) c4[i][j][q] = 0.f;

    for (int c = 0; c < 4; c++) {
        const int buf = c % 3;
        const float* As = Asb + buf * (128 * 36);
        const float* Bs = Bsb + buf * (128 * 36);
        CP_WAIT1();
        __syncthreads();
        if (c + 2 < 4) { prefetch(c + 2, (c + 2) % 3); CP_COMMIT(); }
#pragma unroll
        for (int ks = 0; ks < 32; ks += 8) {
            float a[4][4], bb[4][2];
#pragma unroll
            for (int mi = 0; mi < 4; mi++) {
                int rr = wm * 64 + mi * 16 + g;
                a[mi][0] = As[rr * 36 + ks + tg];     a[mi][1] = As[(rr + 8) * 36 + ks + tg];
                a[mi][2] = As[rr * 36 + ks + tg + 4]; a[mi][3] = As[(rr + 8) * 36 + ks + tg + 4];
            }
#pragma unroll
            for (int ni = 0; ni < 4; ni++) {
                int cc = wn * 32 + ni * 8 + g;
                bb[ni][0] = Bs[cc * 36 + ks + tg]; bb[ni][1] = Bs[cc * 36 + ks + tg + 4];
            }
#pragma unroll
            for (int mi = 0; mi < 4; mi++)
#pragma unroll
                for (int ni = 0; ni < 4; ni++)
                    mma8(c4[mi][ni], a[mi][0], a[mi][1], a[mi][2], a[mi][3],
                         bb[ni][0], bb[ni][1]);
        }
        __syncthreads();
    }
#pragma unroll
    for (int ni = 0; ni < 4; ni++) {
        int col = wn * 32 + ni * 8 + tg * 2;
        float b0 = bias[col], b1 = bias[col + 1];
#pragma unroll
        for (int mi = 0; mi < 4; mi++) {
            int m = m0 + wm * 64 + mi * 16 + g;
            *reinterpret_cast<float2*>(&out[(size_t)m * 128 + col]) =
                make_float2(c4[mi][ni][0] + b0, c4[mi][ni][1] + b1);
            *reinterpret_cast<float2*>(&out[(size_t)(m + 8) * 128 + col]) =
                make_float2(c4[mi][ni][2] + b0, c4[mi][ni][3] + b1);
        }
    }
}

extern "C" void kernel_launch(void* const* d_in, const int* in_sizes, int n_in,
                              void* d_out, int out_size) {
    const float* x      = (const float*)d_in[0];
    const float* mask   = (const float*)d_in[1];
    const float* rpb    = (const float*)d_in[2];
    const float* qkv_w  = (const float*)d_in[3];
    const float* qkv_b  = (const float*)d_in[4];
    const float* proj_w = (const float*)d_in[5];
    const float* proj_b = (const float*)d_in[6];
    const int*   relidx = (const int*)d_in[7];
    float* out = (float*)d_out;

    cudaFuncSetAttribute(k_qkv, cudaFuncAttributeMaxDynamicSharedMemorySize, QKV_SMEM_BYTES);
    cudaFuncSetAttribute(k_attn, cudaFuncAttributeMaxDynamicSharedMemorySize, ATTN_SMEM_BYTES);
    cudaFuncSetAttribute(k_proj, cudaFuncAttributeMaxDynamicSharedMemorySize, PROJ_SMEM_BYTES);

    k_prep<<<192, 256>>>(qkv_w, proj_w);
    k_comb<<<NW * HEADS, 256>>>(mask, rpb, relidx);
    k_qkv<<<BATCH * NTOK / 128, 256, QKV_SMEM_BYTES>>>(x, qkv_b);
    k_attn<<<dim3(8, HEADS, NW), ATHREADS, ATTN_SMEM_BYTES>>>();
    k_proj<<<BATCH * NTOK / 128, 256, PROJ_SMEM_BYTES>>>(proj_b, out);
}